// round 6
// baseline (speedup 1.0000x reference)
#include <cuda_runtime.h>
#include <math.h>

// Problem shapes (fixed by the dataset)
#define N_Q 256      // queries
#define DIM 512      // feature dim
#define QB  2048     // bank size
#define NC  1000     // classes
#define IMG 150528   // 3*224*224
#define IMG4 (IMG/4) // 37632 float4 per image
#define KNN 4

// Output layout (float32, concatenated in reference return order)
#define OFF_LBL 0
#define OFF_PRB 256
#define OFF_IMG 256256           // 256 + 256*1000
#define OFF_GRD 38791424         // OFF_IMG + 256*150528

#define BM 64
#define BN 64
#define BK 32
#define NBX (QB / BN)            // 32 partial top-4 blocks per query

// Scratch (static device globals — no allocations allowed)
__device__ float g_pv[N_Q * NBX * 4];   // partial top-4 values per (q, col-block)
__device__ int   g_pi[N_Q * NBX * 4];   // partial top-4 indices
__device__ int   g_idx[N_Q * KNN];

typedef unsigned long long u64;

// ---------------------------------------------------------------------------
// packed fp32x2 helpers (sm_100+ FFMA2: one issue slot, two FMAs)
// ---------------------------------------------------------------------------
__device__ __forceinline__ void fma2(u64& d, u64 a, u64 b) {
    asm("fma.rn.f32x2 %0, %1, %2, %0;" : "+l"(d) : "l"(a), "l"(b));
}
__device__ __forceinline__ void unpk(u64 v, float& lo, float& hi) {
    asm("mov.b64 {%0, %1}, %2;" : "=f"(lo), "=f"(hi) : "l"(v));
}

// ---------------------------------------------------------------------------
// top-4 helpers: largest-first, ties -> smaller index (lax.top_k order)
// ---------------------------------------------------------------------------
__device__ __forceinline__ bool d_better(float v, int j, float v2, int j2) {
    return (v > v2) || (v == v2 && j < j2);
}
__device__ __forceinline__ void d_insert(float v, int j, float* bv, int* bi) {
    if (!d_better(v, j, bv[3], bi[3])) return;
    int p = 3;
    while (p > 0 && d_better(v, j, bv[p - 1], bi[p - 1])) {
        bv[p] = bv[p - 1]; bi[p] = bi[p - 1]; p--;
    }
    bv[p] = v; bi[p] = j;
}
template<int SPAN>
__device__ __forceinline__ void shfl_merge_top4(float* bv, int* bi) {
#pragma unroll
    for (int o = SPAN / 2; o; o >>= 1) {
        float pv[4]; int pi[4];
#pragma unroll
        for (int k = 0; k < 4; k++) {
            pv[k] = __shfl_xor_sync(0xffffffffu, bv[k], o);
            pi[k] = __shfl_xor_sync(0xffffffffu, bi[k], o);
        }
#pragma unroll
        for (int k = 0; k < 4; k++) d_insert(pv[k], pi[k], bv, bi);
    }
}

// ---------------------------------------------------------------------------
// K1: fused norms + distance GEMM + per-tile top-4 partials.
// Tile 64x64x32, 256 threads, 4x4 micro-tile via packed f32x2 (4x2 pairs).
// grid = (QB/64, N_Q/64) = (32, 4) = 128 CTAs.
// A tile stored as DUPLICATED pairs (a,a): one LDS.64 = ready FFMA2 operand.
// Row norms (asq) and col norms (bsq) accumulate inside the k-loop; since
// every thread sees all 512 k's, no reduction is needed (values replicated).
// ---------------------------------------------------------------------------
#define BMp 65   // As2 row stride in float2 (pad kills STS bank conflicts)
#define BNp 66   // Bs row stride in float
__global__ void dist_topk_kernel(const float* __restrict__ A,   // features (N_Q,DIM)
                                 const float* __restrict__ B) { // bank     (QB,DIM)
    __shared__ float2 As2[BK][BMp];
    __shared__ float  Bs[BK][BNp];
    int tid = threadIdx.x;
    int tx = tid & 15;        // 0..15 -> 4 bank cols
    int ty = tid >> 4;        // 0..15 -> 4 query rows
    int qb = blockIdx.y * BM;
    int bb = blockIdx.x * BN;

    u64 acc[4][2] = {};   // [row][colpair] packed fp32x2
    u64 asq[4] = {};      // (|a_r|^2, |a_r|^2) dup pairs
    u64 bsq[2] = {};      // (|b_j|^2, |b_j+1|^2) pairs

    for (int k0 = 0; k0 < DIM; k0 += BK) {
        // A tile: 64 rows x 8 float4 = 512 float4 -> 2 per thread (dup-store)
#pragma unroll
        for (int l = 0; l < 2; l++) {
            int i  = tid + l * 256;
            int r  = i >> 3;            // 0..63
            int c4 = i & 7;             // 0..7
            float4 v = *(const float4*)(A + (size_t)(qb + r) * DIM + k0 + c4 * 4);
            As2[c4 * 4 + 0][r] = make_float2(v.x, v.x);
            As2[c4 * 4 + 1][r] = make_float2(v.y, v.y);
            As2[c4 * 4 + 2][r] = make_float2(v.z, v.z);
            As2[c4 * 4 + 3][r] = make_float2(v.w, v.w);
            float4 w = *(const float4*)(B + (size_t)(bb + r) * DIM + k0 + c4 * 4);
            Bs[c4 * 4 + 0][r] = w.x; Bs[c4 * 4 + 1][r] = w.y;
            Bs[c4 * 4 + 2][r] = w.z; Bs[c4 * 4 + 3][r] = w.w;
        }
        __syncthreads();
#pragma unroll
        for (int k = 0; k < BK; k++) {
            u64 ra0 = *(const u64*)&As2[k][ty * 4 + 0];
            u64 ra1 = *(const u64*)&As2[k][ty * 4 + 1];
            u64 ra2 = *(const u64*)&As2[k][ty * 4 + 2];
            u64 ra3 = *(const u64*)&As2[k][ty * 4 + 3];
            u64 rb01 = *(const u64*)&Bs[k][tx * 4 + 0];
            u64 rb23 = *(const u64*)&Bs[k][tx * 4 + 2];
            fma2(acc[0][0], ra0, rb01); fma2(acc[0][1], ra0, rb23);
            fma2(acc[1][0], ra1, rb01); fma2(acc[1][1], ra1, rb23);
            fma2(acc[2][0], ra2, rb01); fma2(acc[2][1], ra2, rb23);
            fma2(acc[3][0], ra3, rb01); fma2(acc[3][1], ra3, rb23);
            fma2(asq[0], ra0, ra0); fma2(asq[1], ra1, ra1);
            fma2(asq[2], ra2, ra2); fma2(asq[3], ra3, ra3);
            fma2(bsq[0], rb01, rb01); fma2(bsq[1], rb23, rb23);
        }
        __syncthreads();
    }

    // inverse norms (complete sums, replicated per thread -> no reductions)
    float qinv[4], binv[4];
#pragma unroll
    for (int i = 0; i < 4; i++) {
        float lo, hi; unpk(asq[i], lo, hi);
        qinv[i] = 1.0f / fmaxf(sqrtf(lo), 1e-12f);
    }
    {
        float b0, b1, b2, b3;
        unpk(bsq[0], b0, b1); unpk(bsq[1], b2, b3);
        binv[0] = 1.0f / fmaxf(sqrtf(b0), 1e-12f);
        binv[1] = 1.0f / fmaxf(sqrtf(b1), 1e-12f);
        binv[2] = 1.0f / fmaxf(sqrtf(b2), 1e-12f);
        binv[3] = 1.0f / fmaxf(sqrtf(b3), 1e-12f);
    }

    // epilogue: distances + per-row top-4 over this CTA's 64 columns
#pragma unroll
    for (int i = 0; i < 4; i++) {
        int q = qb + ty * 4 + i;
        float d01l, d01h, d23l, d23h;
        unpk(acc[i][0], d01l, d01h);
        unpk(acc[i][1], d23l, d23h);
        float bv[4] = {-3.0e38f, -3.0e38f, -3.0e38f, -3.0e38f};
        int   bi[4] = {0x7fffffff, 0x7fffffff, 0x7fffffff, 0x7fffffff};
        int b0 = bb + tx * 4;
        d_insert(1.0f - d01l * qinv[i] * binv[0], b0 + 0, bv, bi);
        d_insert(1.0f - d01h * qinv[i] * binv[1], b0 + 1, bv, bi);
        d_insert(1.0f - d23l * qinv[i] * binv[2], b0 + 2, bv, bi);
        d_insert(1.0f - d23h * qinv[i] * binv[3], b0 + 3, bv, bi);
        shfl_merge_top4<16>(bv, bi);   // across the 16 tx lanes of this row
        if (tx == 0) {
            int base = (q * NBX + blockIdx.x) * 4;
#pragma unroll
            for (int k = 0; k < 4; k++) { g_pv[base + k] = bv[k]; g_pi[base + k] = bi[k]; }
        }
    }
}

// ---------------------------------------------------------------------------
// K2: final top-4 merge. One warp per query folds 32 partials x 4 = 128
// candidates. 32 blocks x 256 threads (8 warps each).
// ---------------------------------------------------------------------------
__global__ void merge_topk_kernel() {
    int tid  = threadIdx.x;
    int lane = tid & 31, wid = tid >> 5;
    int q = blockIdx.x * 8 + wid;

    const float4* pv4 = (const float4*)(g_pv + q * NBX * 4);
    const int4*   pi4 = (const int4*)  (g_pi + q * NBX * 4);
    float4 v = pv4[lane];   // 128 candidates = 1 float4 per lane
    int4   j = pi4[lane];

    float bv[4] = {-3.0e38f, -3.0e38f, -3.0e38f, -3.0e38f};
    int   bi[4] = {0x7fffffff, 0x7fffffff, 0x7fffffff, 0x7fffffff};
    d_insert(v.x, j.x, bv, bi);
    d_insert(v.y, j.y, bv, bi);
    d_insert(v.z, j.z, bv, bi);
    d_insert(v.w, j.w, bv, bi);
    shfl_merge_top4<32>(bv, bi);
    if (lane < 4) g_idx[q * 4 + lane] = bi[lane];
}

// ---------------------------------------------------------------------------
// K3: fused gather. grid=(256, 22), 256 threads.
//   blockIdx.y < 21 : pred_images chunk (HBM-bound bulk)
//   blockIdx.y ==21 : grads_m + pred_probs + pred_labels (hidden in the wave)
// ---------------------------------------------------------------------------
__global__ void gather_kernel(const float* __restrict__ img,
                              const float* __restrict__ bank,
                              const float* __restrict__ probs,
                              float* __restrict__ out) {
    int q = blockIdx.x;
    int tid = threadIdx.x;
    __shared__ int ix[4];
    if (tid < 4) ix[tid] = g_idx[q * 4 + tid];
    __syncthreads();

    if (blockIdx.y < 21) {
        const float4* im = (const float4*)img;
        float4* o = (float4*)(out + OFF_IMG) + (size_t)q * IMG4;
        size_t r0 = (size_t)ix[0] * IMG4;
        size_t r1 = (size_t)ix[1] * IMG4;
        size_t r2 = (size_t)ix[2] * IMG4;
        size_t r3 = (size_t)ix[3] * IMG4;
#pragma unroll
        for (int t = 0; t < 7; t++) {
            int f = blockIdx.y * 1792 + t * 256 + tid;   // 21*1792 = 37632 = IMG4
            float4 a = im[r0 + f];
            float4 b = im[r1 + f];
            float4 c = im[r2 + f];
            float4 d = im[r3 + f];
            float4 r;
            r.x = 0.25f * (a.x + b.x + c.x + d.x);
            r.y = 0.25f * (a.y + b.y + c.y + d.y);
            r.z = 0.25f * (a.z + b.z + c.z + d.z);
            r.w = 0.25f * (a.w + b.w + c.w + d.w);
            __stcs(&o[f], r);   // streaming store: no reuse of output
        }
        return;
    }

    // ---- small outputs slice ----
    if (tid < 128) {
        const float4* b0 = (const float4*)(bank + (size_t)ix[0] * DIM);
        const float4* b1 = (const float4*)(bank + (size_t)ix[1] * DIM);
        const float4* b2 = (const float4*)(bank + (size_t)ix[2] * DIM);
        const float4* b3 = (const float4*)(bank + (size_t)ix[3] * DIM);
        float4 a = b0[tid], b = b1[tid], c = b2[tid], d = b3[tid];
        float4 r;
        r.x = 0.25f * (a.x + b.x + c.x + d.x);
        r.y = 0.25f * (a.y + b.y + c.y + d.y);
        r.z = 0.25f * (a.z + b.z + c.z + d.z);
        r.w = 0.25f * (a.w + b.w + c.w + d.w);
        ((float4*)(out + OFF_GRD + (size_t)q * DIM))[tid] = r;
    }

    float bestv = -3.0e38f;
    int   bestc = 0x7fffffff;
    if (tid < 250) {
        const float4* p0 = (const float4*)(probs + (size_t)ix[0] * NC);
        const float4* p1 = (const float4*)(probs + (size_t)ix[1] * NC);
        const float4* p2 = (const float4*)(probs + (size_t)ix[2] * NC);
        const float4* p3 = (const float4*)(probs + (size_t)ix[3] * NC);
        float4 a = p0[tid], b = p1[tid], c = p2[tid], d = p3[tid];
        float4 m;
        m.x = 0.25f * (a.x + b.x + c.x + d.x);
        m.y = 0.25f * (a.y + b.y + c.y + d.y);
        m.z = 0.25f * (a.z + b.z + c.z + d.z);
        m.w = 0.25f * (a.w + b.w + c.w + d.w);
        ((float4*)(out + OFF_PRB + (size_t)q * NC))[tid] = m;
        int c0 = tid * 4;
        bestv = m.x; bestc = c0;
        if (m.y > bestv) { bestv = m.y; bestc = c0 + 1; }
        if (m.z > bestv) { bestv = m.z; bestc = c0 + 2; }
        if (m.w > bestv) { bestv = m.w; bestc = c0 + 3; }
    }
    __shared__ float rv[256];
    __shared__ int   rc[256];
    rv[tid] = bestv; rc[tid] = bestc;
    __syncthreads();
    for (int s = 128; s; s >>= 1) {
        if (tid < s) {
            float v2 = rv[tid + s]; int c2 = rc[tid + s];
            if (v2 > rv[tid] || (v2 == rv[tid] && c2 < rc[tid])) {
                rv[tid] = v2; rc[tid] = c2;
            }
        }
        __syncthreads();
    }
    if (tid == 0) out[OFF_LBL + q] = (float)rc[0];
}

// ---------------------------------------------------------------------------
extern "C" void kernel_launch(void* const* d_in, const int* in_sizes, int n_in,
                              void* d_out, int out_size) {
    const float* feat  = (const float*)d_in[0];
    const float* bank  = (const float*)d_in[1];
    const float* probs = (const float*)d_in[2];
    const float* img   = (const float*)d_in[3];
    float* out = (float*)d_out;

    dist_topk_kernel<<<dim3(QB / BN, N_Q / BM), 256>>>(feat, bank);
    merge_topk_kernel<<<N_Q / 8, 256>>>();
    gather_kernel<<<dim3(N_Q, 22), 256>>>(img, bank, probs, out);
}

// round 7
// speedup vs baseline: 1.1058x; 1.1058x over previous
#include <cuda_runtime.h>
#include <math.h>

// Problem shapes (fixed by the dataset)
#define N_Q 256      // queries
#define DIM 512      // feature dim
#define QB  2048     // bank size
#define NC  1000     // classes
#define IMG 150528   // 3*224*224
#define IMG4 (IMG/4) // 37632 float4 per image
#define KNN 4

// Output layout (float32, concatenated in reference return order)
#define OFF_LBL 0
#define OFF_PRB 256
#define OFF_IMG 256256           // 256 + 256*1000
#define OFF_GRD 38791424         // OFF_IMG + 256*150528

#define BM 64
#define BN 64
#define BK 32
#define NBX (QB / BN)            // 32 partial top-4 blocks per query

// Scratch (static device globals — no allocations allowed)
__device__ float g_qinv[N_Q];
__device__ float g_binv[QB];
__device__ float g_pv[N_Q * NBX * 4];   // partial top-4 values per (q, col-block)
__device__ int   g_pi[N_Q * NBX * 4];   // partial top-4 indices
__device__ int   g_idx[N_Q * KNN];

// ---------------------------------------------------------------------------
// top-4 helpers: largest-first, ties -> smaller index (lax.top_k order)
// ---------------------------------------------------------------------------
__device__ __forceinline__ bool d_better(float v, int j, float v2, int j2) {
    return (v > v2) || (v == v2 && j < j2);
}
__device__ __forceinline__ void d_insert(float v, int j, float* bv, int* bi) {
    if (!d_better(v, j, bv[3], bi[3])) return;
    int p = 3;
    while (p > 0 && d_better(v, j, bv[p - 1], bi[p - 1])) {
        bv[p] = bv[p - 1]; bi[p] = bi[p - 1]; p--;
    }
    bv[p] = v; bi[p] = j;
}
template<int SPAN>
__device__ __forceinline__ void shfl_merge_top4(float* bv, int* bi) {
#pragma unroll
    for (int o = SPAN / 2; o; o >>= 1) {
        float pv[4]; int pi[4];
#pragma unroll
        for (int k = 0; k < 4; k++) {
            pv[k] = __shfl_xor_sync(0xffffffffu, bv[k], o);
            pi[k] = __shfl_xor_sync(0xffffffffu, bi[k], o);
        }
#pragma unroll
        for (int k = 0; k < 4; k++) d_insert(pv[k], pi[k], bv, bi);
    }
}

// ---------------------------------------------------------------------------
// K0: inverse L2 norms for query rows and bank rows (ONE WARP per row)
// ---------------------------------------------------------------------------
__global__ void norms_kernel(const float* __restrict__ feat,
                             const float* __restrict__ bank) {
    int w    = (blockIdx.x * blockDim.x + threadIdx.x) >> 5;
    int lane = threadIdx.x & 31;
    if (w >= N_Q + QB) return;
    const float* row = (w < N_Q) ? feat + (size_t)w * DIM
                                 : bank + (size_t)(w - N_Q) * DIM;
    const float4* r4 = (const float4*)row;
    float s = 0.f;
#pragma unroll
    for (int i = 0; i < 4; i++) {
        float4 v = r4[lane + 32 * i];
        s += v.x * v.x + v.y * v.y + v.z * v.z + v.w * v.w;
    }
#pragma unroll
    for (int o = 16; o; o >>= 1) s += __shfl_xor_sync(0xffffffffu, s, o);
    if (lane == 0) {
        float inv = 1.0f / fmaxf(sqrtf(s), 1e-12f);
        if (w < N_Q) g_qinv[w] = inv;
        else         g_binv[w - N_Q] = inv;
    }
}

// ---------------------------------------------------------------------------
// K1: distance GEMM + fused per-tile top-4 partials.
// Tile 64x64x32, *512 threads* (16 warps/SM -> 4 per SMSP: latency hiding),
// micro-tile 2x4 per thread. Inner loop: 1 LDS.64 (A) + 1 LDS.128 (B) + 8 FMA.
// grid = (QB/64, N_Q/64) = (32, 4) = 128 CTAs, bank streamed 4x (min traffic).
// ---------------------------------------------------------------------------
#define BMp 66   // As row stride in floats (even -> float2 aligned; kills STS conflicts)
#define BNp 68   // Bs row stride in floats (mult of 4 -> float4 aligned)
__global__ void __launch_bounds__(512, 1)
dist_topk_kernel(const float* __restrict__ A,   // features (N_Q,DIM)
                 const float* __restrict__ B) { // bank     (QB,DIM)
    __shared__ float As[BK][BMp];
    __shared__ float Bs[BK][BNp];
    int tid = threadIdx.x;
    int tx = tid & 15;        // 0..15 -> 4 bank cols
    int ty = tid >> 4;        // 0..31 -> 2 query rows
    int qb = blockIdx.y * BM;
    int bb = blockIdx.x * BN;

    float acc[2][4] = {};

    for (int k0 = 0; k0 < DIM; k0 += BK) {
        // Each tile: 64 rows x 32 k = 512 float4; 1 per thread.
        {
            int r  = tid >> 3;          // 0..63
            int c4 = tid & 7;           // 0..7
            float4 v = *(const float4*)(A + (size_t)(qb + r) * DIM + k0 + c4 * 4);
            As[c4 * 4 + 0][r] = v.x; As[c4 * 4 + 1][r] = v.y;
            As[c4 * 4 + 2][r] = v.z; As[c4 * 4 + 3][r] = v.w;
            float4 w = *(const float4*)(B + (size_t)(bb + r) * DIM + k0 + c4 * 4);
            Bs[c4 * 4 + 0][r] = w.x; Bs[c4 * 4 + 1][r] = w.y;
            Bs[c4 * 4 + 2][r] = w.z; Bs[c4 * 4 + 3][r] = w.w;
        }
        __syncthreads();
#pragma unroll
        for (int k = 0; k < BK; k++) {
            float2 a01 = *(const float2*)&As[k][ty * 2];      // LDS.64 (broadcast)
            float4 b   = *(const float4*)&Bs[k][tx * 4];      // LDS.128
            acc[0][0] = fmaf(a01.x, b.x, acc[0][0]);
            acc[0][1] = fmaf(a01.x, b.y, acc[0][1]);
            acc[0][2] = fmaf(a01.x, b.z, acc[0][2]);
            acc[0][3] = fmaf(a01.x, b.w, acc[0][3]);
            acc[1][0] = fmaf(a01.y, b.x, acc[1][0]);
            acc[1][1] = fmaf(a01.y, b.y, acc[1][1]);
            acc[1][2] = fmaf(a01.y, b.z, acc[1][2]);
            acc[1][3] = fmaf(a01.y, b.w, acc[1][3]);
        }
        __syncthreads();
    }

    // Epilogue: distances + per-row top-4 over this CTA's 64 columns.
    float bj[4];
#pragma unroll
    for (int j = 0; j < 4; j++) bj[j] = g_binv[bb + tx * 4 + j];

#pragma unroll
    for (int i = 0; i < 2; i++) {
        int q = qb + ty * 2 + i;
        float qi = g_qinv[q];
        float bv[4] = {-3.0e38f, -3.0e38f, -3.0e38f, -3.0e38f};
        int   bi[4] = {0x7fffffff, 0x7fffffff, 0x7fffffff, 0x7fffffff};
        int b0 = bb + tx * 4;
#pragma unroll
        for (int j = 0; j < 4; j++)
            d_insert(1.0f - acc[i][j] * qi * bj[j], b0 + j, bv, bi);
        // merge across the 16 tx lanes sharing this query row
        shfl_merge_top4<16>(bv, bi);
        if (tx == 0) {
            int base = (q * NBX + blockIdx.x) * 4;
#pragma unroll
            for (int k = 0; k < 4; k++) { g_pv[base + k] = bv[k]; g_pi[base + k] = bi[k]; }
        }
    }
}

// ---------------------------------------------------------------------------
// K2: final top-4 merge. One warp per query folds 32 partials x 4 = 128
// candidates. 32 blocks x 256 threads (8 warps each).
// ---------------------------------------------------------------------------
__global__ void merge_topk_kernel() {
    int tid  = threadIdx.x;
    int lane = tid & 31, wid = tid >> 5;
    int q = blockIdx.x * 8 + wid;

    const float4* pv4 = (const float4*)(g_pv + q * NBX * 4);
    const int4*   pi4 = (const int4*)  (g_pi + q * NBX * 4);
    float4 v = pv4[lane];   // 128 candidates = 1 float4 per lane
    int4   j = pi4[lane];

    float bv[4] = {-3.0e38f, -3.0e38f, -3.0e38f, -3.0e38f};
    int   bi[4] = {0x7fffffff, 0x7fffffff, 0x7fffffff, 0x7fffffff};
    d_insert(v.x, j.x, bv, bi);
    d_insert(v.y, j.y, bv, bi);
    d_insert(v.z, j.z, bv, bi);
    d_insert(v.w, j.w, bv, bi);
    shfl_merge_top4<32>(bv, bi);
    if (lane < 4) g_idx[q * 4 + lane] = bi[lane];
}

// ---------------------------------------------------------------------------
// K3: fused gather. grid=(256, 22), 256 threads.
//   blockIdx.y < 21 : pred_images chunk (HBM-bound bulk)
//   blockIdx.y ==21 : grads_m + pred_probs + pred_labels (hidden in the wave)
// ---------------------------------------------------------------------------
__global__ void gather_kernel(const float* __restrict__ img,
                              const float* __restrict__ bank,
                              const float* __restrict__ probs,
                              float* __restrict__ out) {
    int q = blockIdx.x;
    int tid = threadIdx.x;
    __shared__ int ix[4];
    if (tid < 4) ix[tid] = g_idx[q * 4 + tid];
    __syncthreads();

    if (blockIdx.y < 21) {
        const float4* im = (const float4*)img;
        float4* o = (float4*)(out + OFF_IMG) + (size_t)q * IMG4;
        size_t r0 = (size_t)ix[0] * IMG4;
        size_t r1 = (size_t)ix[1] * IMG4;
        size_t r2 = (size_t)ix[2] * IMG4;
        size_t r3 = (size_t)ix[3] * IMG4;
#pragma unroll
        for (int t = 0; t < 7; t++) {
            int f = blockIdx.y * 1792 + t * 256 + tid;   // 21*1792 = 37632 = IMG4
            float4 a = im[r0 + f];
            float4 b = im[r1 + f];
            float4 c = im[r2 + f];
            float4 d = im[r3 + f];
            float4 r;
            r.x = 0.25f * (a.x + b.x + c.x + d.x);
            r.y = 0.25f * (a.y + b.y + c.y + d.y);
            r.z = 0.25f * (a.z + b.z + c.z + d.z);
            r.w = 0.25f * (a.w + b.w + c.w + d.w);
            __stcs(&o[f], r);   // streaming store: no reuse of output
        }
        return;
    }

    // ---- small outputs slice ----
    if (tid < 128) {
        const float4* b0 = (const float4*)(bank + (size_t)ix[0] * DIM);
        const float4* b1 = (const float4*)(bank + (size_t)ix[1] * DIM);
        const float4* b2 = (const float4*)(bank + (size_t)ix[2] * DIM);
        const float4* b3 = (const float4*)(bank + (size_t)ix[3] * DIM);
        float4 a = b0[tid], b = b1[tid], c = b2[tid], d = b3[tid];
        float4 r;
        r.x = 0.25f * (a.x + b.x + c.x + d.x);
        r.y = 0.25f * (a.y + b.y + c.y + d.y);
        r.z = 0.25f * (a.z + b.z + c.z + d.z);
        r.w = 0.25f * (a.w + b.w + c.w + d.w);
        ((float4*)(out + OFF_GRD + (size_t)q * DIM))[tid] = r;
    }

    float bestv = -3.0e38f;
    int   bestc = 0x7fffffff;
    if (tid < 250) {
        const float4* p0 = (const float4*)(probs + (size_t)ix[0] * NC);
        const float4* p1 = (const float4*)(probs + (size_t)ix[1] * NC);
        const float4* p2 = (const float4*)(probs + (size_t)ix[2] * NC);
        const float4* p3 = (const float4*)(probs + (size_t)ix[3] * NC);
        float4 a = p0[tid], b = p1[tid], c = p2[tid], d = p3[tid];
        float4 m;
        m.x = 0.25f * (a.x + b.x + c.x + d.x);
        m.y = 0.25f * (a.y + b.y + c.y + d.y);
        m.z = 0.25f * (a.z + b.z + c.z + d.z);
        m.w = 0.25f * (a.w + b.w + c.w + d.w);
        ((float4*)(out + OFF_PRB + (size_t)q * NC))[tid] = m;
        int c0 = tid * 4;
        bestv = m.x; bestc = c0;
        if (m.y > bestv) { bestv = m.y; bestc = c0 + 1; }
        if (m.z > bestv) { bestv = m.z; bestc = c0 + 2; }
        if (m.w > bestv) { bestv = m.w; bestc = c0 + 3; }
    }
    __shared__ float rv[256];
    __shared__ int   rc[256];
    rv[tid] = bestv; rc[tid] = bestc;
    __syncthreads();
    for (int s = 128; s; s >>= 1) {
        if (tid < s) {
            float v2 = rv[tid + s]; int c2 = rc[tid + s];
            if (v2 > rv[tid] || (v2 == rv[tid] && c2 < rc[tid])) {
                rv[tid] = v2; rc[tid] = c2;
            }
        }
        __syncthreads();
    }
    if (tid == 0) out[OFF_LBL + q] = (float)rc[0];
}

// ---------------------------------------------------------------------------
extern "C" void kernel_launch(void* const* d_in, const int* in_sizes, int n_in,
                              void* d_out, int out_size) {
    const float* feat  = (const float*)d_in[0];
    const float* bank  = (const float*)d_in[1];
    const float* probs = (const float*)d_in[2];
    const float* img   = (const float*)d_in[3];
    float* out = (float*)d_out;

    norms_kernel<<<((N_Q + QB) * 32 + 255) / 256, 256>>>(feat, bank);
    dist_topk_kernel<<<dim3(QB / BN, N_Q / BM), 512>>>(feat, bank);
    merge_topk_kernel<<<N_Q / 8, 256>>>();
    gather_kernel<<<dim3(N_Q, 22), 256>>>(img, bank, probs, out);
}